// round 3
// baseline (speedup 1.0000x reference)
#include <cuda_runtime.h>
#include <cuda_bf16.h>
#include <cstdint>

// Problem dims
#define NB   32
#define C    256
#define H    56
#define W    56
#define HP   58
#define WP   58
#define MP   (NB*HP*WP)        // 107648 padded-flat rows (multiple of 128: 841*128)
#define MPAD 128               // extra zero rows for tap offsets (max 2*58+2=118)
#define NVALID (NB*H*W)        // 100352

// GEMM tiling
#define BM 128
#define BN 128
#define BK 32
#define SROW 40                // padded smem row stride (elements)

// -------- device scratch (no allocations allowed) --------
__device__ __nv_bfloat16 g_xb[(size_t)(MP + MPAD) * C];   // padded NHWC binarized x (+safety pad)
__device__ __nv_bfloat16 g_wb[9 * 256 * 256];             // [tap][cout][cin] binarized w
__device__ short         g_y[(size_t)MP * 256];           // conv result per (padded row, cout)
__device__ int           g_sum[256];
__device__ long long     g_sumsq[256];
__device__ float         g_scale[256];
__device__ float         g_shift[256];

// -------- asm helpers --------
__device__ __forceinline__ uint32_t smem_u32(const void* p) {
    return (uint32_t)__cvta_generic_to_shared(p);
}
__device__ __forceinline__ void ldsm4(uint32_t& r0, uint32_t& r1, uint32_t& r2, uint32_t& r3, uint32_t a) {
    asm volatile("ldmatrix.sync.aligned.m8n8.x4.shared.b16 {%0,%1,%2,%3}, [%4];"
                 : "=r"(r0), "=r"(r1), "=r"(r2), "=r"(r3) : "r"(a));
}
__device__ __forceinline__ void mma16816(float* d, const uint32_t* a, uint32_t b0, uint32_t b1) {
    asm volatile("mma.sync.aligned.m16n8k16.row.col.f32.bf16.bf16.f32 "
                 "{%0,%1,%2,%3},{%4,%5,%6,%7},{%8,%9},{%0,%1,%2,%3};"
                 : "+f"(d[0]), "+f"(d[1]), "+f"(d[2]), "+f"(d[3])
                 : "r"(a[0]), "r"(a[1]), "r"(a[2]), "r"(a[3]), "r"(b0), "r"(b1));
}
__device__ __forceinline__ void cpasync16(uint32_t dst, const void* src) {
    asm volatile("cp.async.cg.shared.global [%0], [%1], 16;" :: "r"(dst), "l"(src));
}
__device__ __forceinline__ void cpcommit() { asm volatile("cp.async.commit_group;"); }
template <int N> __device__ __forceinline__ void cpwait() { asm volatile("cp.async.wait_group %0;" :: "n"(N)); }

// -------- kernel 0: zero scratch (xb borders/pad + stats). Must run every launch. --------
__global__ void zero_kernel() {
    size_t i = (size_t)blockIdx.x * blockDim.x + threadIdx.x;
    const size_t nchunk = ((size_t)(MP + MPAD) * C * 2) / 16;  // 16B chunks
    if (i < nchunk) reinterpret_cast<float4*>(g_xb)[i] = make_float4(0.f, 0.f, 0.f, 0.f);
    if (i < 256) { g_sum[i] = 0; g_sumsq[i] = 0; }
}

// -------- kernel 1: binarize+transpose x NCHW(f32) -> padded NHWC(bf16 +-1) --------
__global__ void pack_x_kernel(const float* __restrict__ x) {
    __shared__ __nv_bfloat16 t[32][34];
    const int tx = threadIdx.x, ty = threadIdx.y;
    const int bz = blockIdx.z;              // n*56 + h
    const int n = bz / 56, h = bz % 56;
    const int w0 = blockIdx.x * 32, c0 = blockIdx.y * 32;
    const __nv_bfloat16 P1 = __float2bfloat16(1.0f);
    const __nv_bfloat16 M1 = __float2bfloat16(-1.0f);
#pragma unroll
    for (int j = 0; j < 4; j++) {
        int c = c0 + ty + j * 8;
        int w = w0 + tx;
        if (w < W) {
            float v = x[(((size_t)n * C + c) * H + h) * W + w];
            t[ty + j * 8][tx] = (v >= 0.f) ? P1 : M1;
        }
    }
    __syncthreads();
#pragma unroll
    for (int j = 0; j < 4; j++) {
        int wl = ty + j * 8;
        int w = w0 + wl;
        if (w < W) {
            int c = c0 + tx;
            g_xb[(((size_t)(n * HP + h + 1)) * WP + (w + 1)) * C + c] = t[tx][wl];
        }
    }
}

// -------- kernel 2: binarize w OIHW -> [tap][cout][cin] bf16 --------
__global__ void pack_w_kernel(const float* __restrict__ w) {
    int g = blockIdx.x * blockDim.x + threadIdx.x;     // 65536 = co*256+ci
    if (g >= 65536) return;
    const float* wp = w + (size_t)g * 9;
    const __nv_bfloat16 P1 = __float2bfloat16(1.0f);
    const __nv_bfloat16 M1 = __float2bfloat16(-1.0f);
#pragma unroll
    for (int t = 0; t < 9; t++) {
        g_wb[(size_t)t * 65536 + g] = (wp[t] >= 0.f) ? P1 : M1;
    }
}

// -------- kernel 3: implicit-GEMM binary conv, y stored int16 [m][cout] --------
__global__ void __launch_bounds__(256, 2) conv_kernel() {
    __shared__ __align__(16) __nv_bfloat16 sA[2][BM * SROW];
    __shared__ __align__(16) __nv_bfloat16 sB[2][BN * SROW];
    const int tid = threadIdx.x;
    const int lane = tid & 31;
    const int warp = tid >> 5;
    const int wm = warp & 1;       // 2 warps along M
    const int wn = warp >> 1;      // 4 warps along N
    const size_t mbase = (size_t)blockIdx.x * BM;
    const int nbase = blockIdx.y * BN;

    const int lrow = tid >> 2;         // 0..63
    const int lcol = (tid & 3) * 8;    // element offset within 32-wide chunk

    float acc[4][4][4];
#pragma unroll
    for (int a = 0; a < 4; a++)
#pragma unroll
        for (int b = 0; b < 4; b++)
#pragma unroll
            for (int c = 0; c < 4; c++) acc[a][b][c] = 0.f;

    auto issue_stage = [&](int s, int it) {
        int t = it >> 3;               // tap 0..8
        int kc = (it & 7) * BK;        // k chunk within 256
        int kh = t / 3, kw = t - kh * 3;
        int off = kh * WP + kw;        // padded-flat row offset for this tap
        const __nv_bfloat16* gA = g_xb + (mbase + (size_t)off) * C + kc + lcol;
        const __nv_bfloat16* gB = g_wb + ((size_t)t * 65536) + (size_t)nbase * 256 + kc + lcol;
#pragma unroll
        for (int p = 0; p < 2; p++) {
            int r = lrow + p * 64;
            cpasync16(smem_u32(&sA[s][r * SROW + lcol]), gA + (size_t)r * C);
            cpasync16(smem_u32(&sB[s][r * SROW + lcol]), gB + (size_t)r * 256);
        }
    };

    issue_stage(0, 0);
    cpcommit();

    const int ITERS = 72;   // 9 taps * 8 k-chunks
    for (int it = 0; it < ITERS; ++it) {
        int s = it & 1;
        if (it < ITERS - 1) {
            issue_stage(s ^ 1, it + 1);
            cpcommit();
            cpwait<1>();
        } else {
            cpwait<0>();
        }
        __syncthreads();
#pragma unroll
        for (int kf = 0; kf < 2; ++kf) {
            uint32_t a[4][4], b[2][4];
            int colo = kf * 16 + (lane >> 4) * 8;
#pragma unroll
            for (int mf = 0; mf < 4; ++mf) {
                int row = wm * 64 + mf * 16 + (lane & 15);
                ldsm4(a[mf][0], a[mf][1], a[mf][2], a[mf][3], smem_u32(&sA[s][row * SROW + colo]));
            }
#pragma unroll
            for (int nh = 0; nh < 2; ++nh) {
                int row = wn * 32 + nh * 16 + (lane & 15);
                ldsm4(b[nh][0], b[nh][1], b[nh][2], b[nh][3], smem_u32(&sB[s][row * SROW + colo]));
            }
#pragma unroll
            for (int mf = 0; mf < 4; ++mf)
#pragma unroll
                for (int nf = 0; nf < 4; ++nf) {
                    int nh = nf >> 1, sel = nf & 1;
                    mma16816(acc[mf][nf], a[mf], b[nh][sel], b[nh][sel | 2]);
                }
        }
        __syncthreads();
    }

    // epilogue: exact integer conv results -> int16 [m][cout]
#pragma unroll
    for (int mf = 0; mf < 4; ++mf) {
        size_t m0 = mbase + wm * 64 + mf * 16 + (lane >> 2);
#pragma unroll
        for (int nf = 0; nf < 4; ++nf) {
            int co = nbase + wn * 32 + nf * 8 + (lane & 3) * 2;
            short2 v0 = make_short2((short)__float2int_rn(acc[mf][nf][0]),
                                    (short)__float2int_rn(acc[mf][nf][1]));
            short2 v1 = make_short2((short)__float2int_rn(acc[mf][nf][2]),
                                    (short)__float2int_rn(acc[mf][nf][3]));
            *reinterpret_cast<short2*>(&g_y[m0 * 256 + co]) = v0;
            *reinterpret_cast<short2*>(&g_y[(m0 + 8) * 256 + co]) = v1;
        }
    }
}

// -------- kernel 4: per-channel integer sums over VALID pixels (deterministic) --------
__global__ void stats_kernel() {
    const int co = threadIdx.x;          // 256 threads = 256 channels
    const int b = blockIdx.x;            // 256 blocks x 392 rows = 100352 valid rows
    int sum = 0;
    long long sq = 0;
    for (int r = 0; r < 392; r++) {
        int v = b * 392 + r;
        int n = v / 3136;
        int rem = v - n * 3136;
        int h = rem / 56;
        int w = rem - h * 56;
        size_t m = ((size_t)(n * HP + h)) * WP + w;   // valid output (h,w) lives at padded (h,w)
        int s = g_y[m * 256 + co];
        sum += s;
        sq += (long long)(s * s);
    }
    atomicAdd(&g_sum[co], sum);
    atomicAdd(reinterpret_cast<unsigned long long*>(&g_sumsq[co]), (unsigned long long)sq);
}

// -------- kernel 5: finalize BN params --------
__global__ void finalize_kernel(const float* __restrict__ gamma, const float* __restrict__ beta) {
    int c = threadIdx.x;
    const double n = (double)NVALID;
    double mean = (double)g_sum[c] / n;
    double var = (double)g_sumsq[c] / n - mean * mean;
    float inv = rsqrtf((float)var + 1e-5f);
    float sc = gamma[c] * inv;
    g_scale[c] = sc;
    g_shift[c] = beta[c] - (float)mean * sc;
}

// -------- kernel 6: normalize + transpose [m][cout] -> NCHW f32 output --------
__global__ void normalize_kernel(float* __restrict__ out) {
    __shared__ float t[32][33];
    const int tx = threadIdx.x, ty = threadIdx.y;
    const int bz = blockIdx.z;            // n*56 + h
    const int n = bz / 56, h = bz % 56;
    const int w0 = blockIdx.x * 32, c0 = blockIdx.y * 32;
    const size_t m0 = ((size_t)(n * HP + h)) * WP;
#pragma unroll
    for (int j = 0; j < 4; j++) {
        int wl = ty + j * 8;
        int w = w0 + wl;
        if (w < W) {
            t[wl][tx] = (float)g_y[(m0 + w) * 256 + c0 + tx];
        }
    }
    __syncthreads();
#pragma unroll
    for (int j = 0; j < 4; j++) {
        int cl = ty + j * 8;
        int c = c0 + cl;
        int w = w0 + tx;
        if (w < W) {
            out[(((size_t)n * C + c) * H + h) * W + w] = t[tx][cl] * g_scale[c] + g_shift[c];
        }
    }
}

extern "C" void kernel_launch(void* const* d_in, const int* in_sizes, int n_in,
                              void* d_out, int out_size) {
    const float* x     = (const float*)d_in[0];
    const float* w     = (const float*)d_in[1];
    const float* gamma = (const float*)d_in[2];
    const float* beta  = (const float*)d_in[3];
    float* out = (float*)d_out;
    (void)in_sizes; (void)n_in; (void)out_size;

    // 0) zero xb (borders + pad) and stats accumulators
    {
        const size_t nchunk = ((size_t)(MP + MPAD) * C * 2) / 16;
        int blocks = (int)((nchunk + 255) / 256);
        zero_kernel<<<blocks, 256>>>();
    }
    // 1) binarize/pad/transpose x
    {
        dim3 grid(2, 8, NB * H);
        dim3 block(32, 8);
        pack_x_kernel<<<grid, block>>>(x);
    }
    // 2) binarize w
    pack_w_kernel<<<256, 256>>>(w);
    // 3) conv (implicit GEMM over padded-flat rows)
    {
        dim3 grid(MP / BM, 256 / BN);   // 841 x 2
        conv_kernel<<<grid, 256>>>();
    }
    // 4) per-channel sums
    stats_kernel<<<256, 256>>>();
    // 5) BN params
    finalize_kernel<<<1, 256>>>(gamma, beta);
    // 6) normalize + layout back to NCHW
    {
        dim3 grid(2, 8, NB * H);
        dim3 block(32, 8);
        normalize_kernel<<<grid, block>>>(out);
    }
}